// round 13
// baseline (speedup 1.0000x reference)
#include <cuda_runtime.h>
#include <math.h>
#include <stdint.h>
#include <limits.h>

// ---------------------------------------------------------------------------
// Quantizer: x [4,16,1024] f32, codebook [65536,16] f32.
// out[0:65536] = nearest codebook entry per token, [B,D,T]; out[65536] = loss.
//
// 4 launches, NO intermediate tile table:
//   prepA : per-block |.| maxima partials
//   prepB : reduce partials -> scales; quantize codebook; reset imax/best/bar
//   scan  : PERSISTENT fused kernel (512 CTAs, all resident):
//           phase A: int8 dp4a tile maxima + atomicMax per-token int max
//           global software barrier
//           phase B: warp-cooperative exact fp32 rescue of candidate tiles,
//                    atomicMax of packed (score,~idx) key  (deterministic)
//   gather: unpack keys, write output, fused deterministic fixed-point loss
// ---------------------------------------------------------------------------

#define TOKENS   4096
#define NCODES   65536
#define DIM      16
#define STC      64                  // codes per tile
#define TPC      8                   // tiles per scan CTA
#define NGR      128                 // scan groups (grid.y)
#define SCTA     (4 * NGR)           // 512 scan CTAs (all resident: 4/SM*148)
#define PBLK     256
#define GGRID    (TOKENS / 256)      // 16 gather CTAs
#define NINF     __int_as_float(0xff800000)
#define FULL     0xffffffffu
#define LSCALE   4294967296.0        // 2^32 fixed-point loss scale

__device__ float    g_part[PBLK * 4];
__device__ unsigned g_scal[4];            // maxX, maxC, SAc (float bits)
__device__ int4     g_Bq[NCODES];         // packed int8 codes, 1 MB
__device__ int      g_bias[NCODES];       // bias in int score units
__device__ int      g_imax[TOKENS];       // per-token int score max
__device__ unsigned long long g_best[TOKENS]; // packed (scoreOrd, ~idx)
__device__ unsigned g_bar;                // global barrier counter
__device__ unsigned long long g_lsum;
__device__ unsigned g_cnt;

__device__ __forceinline__ void cpasync16(const void* dst_smem, const void* src) {
    unsigned s = (unsigned)__cvta_generic_to_shared(dst_smem);
    asm volatile("cp.async.cg.shared.global [%0], [%1], 16;" :: "r"(s), "l"(src));
}
#define CP_COMMIT() asm volatile("cp.async.commit_group;")
#define CP_WAIT0()  asm volatile("cp.async.wait_group 0;")

__device__ __forceinline__ int pack4(int a0, int a1, int a2, int a3) {
    return (a0 & 0xFF) | ((a1 & 0xFF) << 8) | ((a2 & 0xFF) << 16) | (a3 << 24);
}

// ---------------------------------------------------------------------------
// prepA: per-block maxima of |x|, max|c|, Sum|c| -> g_part.
// ---------------------------------------------------------------------------
__global__ __launch_bounds__(256) void prepA_kernel(const float* __restrict__ x,
                                                    const float* __restrict__ cb) {
    __shared__ float sm[3][256];
    int i = blockIdx.x * 256 + threadIdx.x;          // 0..65535
    float ax = fabsf(x[i]);
    const float4* c4 = (const float4*)(cb + (size_t)i * DIM);
    float mc = 0.0f, sa = 0.0f;
#pragma unroll
    for (int v = 0; v < 4; v++) {
        float4 q = c4[v];
        float a0 = fabsf(q.x), a1 = fabsf(q.y), a2 = fabsf(q.z), a3 = fabsf(q.w);
        mc = fmaxf(fmaxf(mc, fmaxf(a0, a1)), fmaxf(a2, a3));
        sa += a0; sa += a1; sa += a2; sa += a3;
    }
    sm[0][threadIdx.x] = ax; sm[1][threadIdx.x] = mc; sm[2][threadIdx.x] = sa;
    __syncthreads();
    for (int s = 128; s > 0; s >>= 1) {
        if (threadIdx.x < s) {
#pragma unroll
            for (int k = 0; k < 3; k++)
                sm[k][threadIdx.x] = fmaxf(sm[k][threadIdx.x], sm[k][threadIdx.x + s]);
        }
        __syncthreads();
    }
    if (threadIdx.x < 3) g_part[blockIdx.x * 4 + threadIdx.x] = sm[threadIdx.x][0];
}

// ---------------------------------------------------------------------------
// prepB: reduce partials, publish scales, quantize codebook, reset state.
// ---------------------------------------------------------------------------
__global__ __launch_bounds__(256) void prepB_kernel(const float* __restrict__ cb) {
    __shared__ float sm[3][256];
    const int tid = threadIdx.x;
    sm[0][tid] = g_part[tid * 4 + 0];
    sm[1][tid] = g_part[tid * 4 + 1];
    sm[2][tid] = g_part[tid * 4 + 2];
    __syncthreads();
    for (int s = 128; s > 0; s >>= 1) {
        if (tid < s) {
#pragma unroll
            for (int k = 0; k < 3; k++)
                sm[k][tid] = fmaxf(sm[k][tid], sm[k][tid + s]);
        }
        __syncthreads();
    }
    const float maxX = sm[0][0], maxC = sm[1][0], SAc = sm[2][0];
    int gidx = blockIdx.x * 256 + tid;
    if (gidx < TOKENS) {                      // per-replay state reset
        g_imax[gidx] = INT_MIN;
        g_best[gidx] = 0ull;
    }
    if (gidx == 0) {
        g_scal[0] = __float_as_uint(maxX);
        g_scal[1] = __float_as_uint(maxC);
        g_scal[2] = __float_as_uint(SAc);
        g_bar  = 0u;
        g_lsum = 0ull;
        g_cnt  = 0u;
    }

    const float sx = maxX * (1.0f / 127.0f);
    const float sc = maxC * (1.0f / 127.0f);
    const float qc = 127.0f / maxC;
    const float4* c4 = (const float4*)(cb + (size_t)gidx * DIM);
    int q[DIM];
    float h = 0.0f;
#pragma unroll
    for (int v = 0; v < 4; v++) {
        float4 p = c4[v];
        h = fmaf(p.x, p.x, h); q[v * 4 + 0] = __float2int_rn(p.x * qc);
        h = fmaf(p.y, p.y, h); q[v * 4 + 1] = __float2int_rn(p.y * qc);
        h = fmaf(p.z, p.z, h); q[v * 4 + 2] = __float2int_rn(p.z * qc);
        h = fmaf(p.w, p.w, h); q[v * 4 + 3] = __float2int_rn(p.w * qc);
    }
    int4 w;
    w.x = pack4(q[0], q[1], q[2], q[3]);
    w.y = pack4(q[4], q[5], q[6], q[7]);
    w.z = pack4(q[8], q[9], q[10], q[11]);
    w.w = pack4(q[12], q[13], q[14], q[15]);
    g_Bq[gidx] = w;
    g_bias[gidx] = __float2int_rn(-0.5f * h / (sx * sc));
}

// ---------------------------------------------------------------------------
// scan: persistent fused kernel. grid (4 batches, 128 groups) = 512 CTAs,
// 256 thr, 4 CTAs/SM (all resident -> safe global barrier).
// ---------------------------------------------------------------------------
__global__ __launch_bounds__(256, 4) void scan_kernel(const float* __restrict__ x,
                                                      const float* __restrict__ cb) {
    __shared__ int4 sQ[TPC * STC];     // 8 KB (512 code rows)
    __shared__ int  sB[TPC * STC];     // 2 KB

    const int tid  = threadIdx.x;
    const int lane = tid & 31;
    const int wbase = tid & ~31;
    const int batch = blockIdx.x;              // 0..3
    const int grp = blockIdx.y;                // 0..127
    const int c0 = grp * (TPC * STC);

    cpasync16(&sQ[tid], &g_Bq[c0 + tid]);
    cpasync16(&sQ[tid + 256], &g_Bq[c0 + tid + 256]);
    if (tid < 128) cpasync16(&sB[tid * 4], &g_bias[c0 + tid * 4]);
    CP_COMMIT();

    const float maxX = __uint_as_float(g_scal[0]);
    const float maxC = __uint_as_float(g_scal[1]);
    const float SAc  = __uint_as_float(g_scal[2]);
    const float sx = maxX * (1.0f / 127.0f);
    const float sc = maxC * (1.0f / 127.0f);
    const float s  = sx * sc;
    const float qx = 127.0f / maxX;

    // quantize 4 tokens; track Sum|x| per token for the error bound
    const float* xp = x + (size_t)batch * (DIM * 1024);
    int   xq[4][4];
    float sax[4];
#pragma unroll
    for (int tk = 0; tk < 4; tk++) {
        int t = tk * 256 + tid;
        float sa = 0.0f;
#pragma unroll
        for (int w = 0; w < 4; w++) {
            float f0 = xp[(w * 4 + 0) * 1024 + t];
            float f1 = xp[(w * 4 + 1) * 1024 + t];
            float f2 = xp[(w * 4 + 2) * 1024 + t];
            float f3 = xp[(w * 4 + 3) * 1024 + t];
            sa += fabsf(f0) + fabsf(f1) + fabsf(f2) + fabsf(f3);
            xq[tk][w] = pack4(__float2int_rn(f0 * qx), __float2int_rn(f1 * qx),
                              __float2int_rn(f2 * qx), __float2int_rn(f3 * qx));
        }
        sax[tk] = sa;
    }

    CP_WAIT0();
    __syncthreads();

    // ---- phase A: dp4a tile maxima ----
    int m8[4][TPC];
    const int4* b4 = (const int4*)sB;
#pragma unroll
    for (int st = 0; st < TPC; st++) {
        int m[4];
#pragma unroll
        for (int tk = 0; tk < 4; tk++) m[tk] = INT_MIN;
#pragma unroll 4
        for (int g = 0; g < STC / 4; g++) {
            int4 bb = b4[st * (STC / 4) + g];
            int bias[4] = {bb.x, bb.y, bb.z, bb.w};
#pragma unroll
            for (int u = 0; u < 4; u++) {
                int4 q = sQ[st * STC + g * 4 + u];
#pragma unroll
                for (int tk = 0; tk < 4; tk++) {
                    int a = __dp4a(q.x, xq[tk][0], bias[u]);
                    a = __dp4a(q.y, xq[tk][1], a);
                    a = __dp4a(q.z, xq[tk][2], a);
                    a = __dp4a(q.w, xq[tk][3], a);
                    m[tk] = max(m[tk], a);
                }
            }
        }
#pragma unroll
        for (int tk = 0; tk < 4; tk++) m8[tk][st] = m[tk];
    }

    // per-token global int max (RED.MAX: order-independent, deterministic)
#pragma unroll
    for (int tk = 0; tk < 4; tk++) {
        int tmax = m8[tk][0];
#pragma unroll
        for (int st = 1; st < TPC; st++) tmax = max(tmax, m8[tk][st]);
        atomicMax(&g_imax[batch * 1024 + tk * 256 + tid], tmax);
    }

    // ---- global barrier (all 512 CTAs resident) ----
    __syncthreads();
    if (tid == 0) {
        __threadfence();
        atomicAdd(&g_bar, 1u);
        while (*(volatile unsigned*)&g_bar < SCTA) { }
    }
    __syncthreads();
    __threadfence();

    // ---- phase B: warp-cooperative exact rescue of candidate tiles ----
    int thr[4];
#pragma unroll
    for (int tk = 0; tk < 4; tk++) {
        int imax = *(volatile int*)&g_imax[batch * 1024 + tk * 256 + tid];
        float E = 0.5f * sc * sax[tk] + 0.5f * sx * SAc
                + 16.0f * sx * sc + sx * sc + 1e-2f;
        thr[tk] = imax - (int)ceilf(2.0f * E / s);
    }

#pragma unroll
    for (int tk = 0; tk < 4; tk++) {
#pragma unroll
        for (int st = 0; st < TPC; st++) {
            unsigned bal = __ballot_sync(FULL, m8[tk][st] >= thr[tk]);
            while (bal) {
                int w = __ffs(bal) - 1;
                bal &= bal - 1;
                int tokw = batch * 1024 + tk * 256 + wbase + w;
                int tw = tokw & 1023;
                float xr[DIM];
#pragma unroll
                for (int d = 0; d < DIM; d++)       // broadcast loads (L1/L2 hot)
                    xr[d] = x[(size_t)batch * (DIM * 1024) + d * 1024 + tw];
                int cbase = (grp * TPC + st) * STC;
                float best = NINF;
                int   bi   = 0;
#pragma unroll
                for (int half = 0; half < 2; half++) {
                    int c = cbase + half * 32 + lane;
                    const float4* cr = (const float4*)(cb + (size_t)c * DIM);
                    float acc = 0.0f, h = 0.0f;
#pragma unroll
                    for (int v4 = 0; v4 < 4; v4++) {
                        float4 q = cr[v4];
                        acc = fmaf(q.x, xr[v4 * 4 + 0], acc); h = fmaf(q.x, q.x, h);
                        acc = fmaf(q.y, xr[v4 * 4 + 1], acc); h = fmaf(q.y, q.y, h);
                        acc = fmaf(q.z, xr[v4 * 4 + 2], acc); h = fmaf(q.z, q.z, h);
                        acc = fmaf(q.w, xr[v4 * 4 + 3], acc); h = fmaf(q.w, q.w, h);
                    }
                    float sscore = acc - 0.5f * h;
                    if (sscore > best || (sscore == best && c < bi)) {
                        best = sscore; bi = c;
                    }
                }
#pragma unroll
                for (int off = 16; off > 0; off >>= 1) {
                    float vb = __shfl_xor_sync(FULL, best, off);
                    int   ib = __shfl_xor_sync(FULL, bi,   off);
                    if (vb > best || (vb == best && ib < bi)) { best = vb; bi = ib; }
                }
                if (lane == 0) {
                    unsigned so = __float_as_uint(best);
                    so = (so & 0x80000000u) ? ~so : (so | 0x80000000u);
                    unsigned long long key =
                        ((unsigned long long)so << 32) | (unsigned)(~bi);
                    atomicMax(&g_best[tokw], key);   // max score, ties -> min idx
                }
            }
        }
    }
}

// ---------------------------------------------------------------------------
// gather: unpack winners, write [B,D,T] output, fused deterministic loss.
// ---------------------------------------------------------------------------
__global__ __launch_bounds__(256) void gather_kernel(const float* __restrict__ x,
                                                     const float* __restrict__ cb,
                                                     float* __restrict__ out,
                                                     int out_size) {
    __shared__ float sh[256];
    const int tid = threadIdx.x;
    const int token = blockIdx.x * 256 + tid;
    const int bb = token >> 10, t = token & 1023;

    unsigned long long key = *(volatile unsigned long long*)&g_best[token];
    int code = (int)(~(unsigned)key);      // lower 32 bits hold ~idx

    const float* q = cb + (size_t)code * DIM;
    float err = 0.0f;
#pragma unroll
    for (int d = 0; d < DIM; d++) {
        float qd = q[d];
        float xd = x[(size_t)bb * (DIM * 1024) + d * 1024 + t];
        float df = qd - xd;
        err = fmaf(df, df, err);
        out[(size_t)bb * (DIM * 1024) + d * 1024 + t] = qd;
    }

    sh[tid] = err;
    __syncthreads();
    for (int s = 128; s > 0; s >>= 1) {
        if (tid < s) sh[tid] += sh[tid + s];
        __syncthreads();
    }
    if (tid == 0) {
        unsigned long long r =
            (unsigned long long)__double2ll_rn((double)sh[0] * LSCALE);
        atomicAdd(&g_lsum, r);
        __threadfence();
        unsigned ticket = atomicAdd(&g_cnt, 1u);
        if (ticket == GGRID - 1 && out_size > NCODES) {
            double sum = (double)*(volatile unsigned long long*)&g_lsum;
            out[NCODES] = (float)(sum / LSCALE / (double)(TOKENS * DIM));
        }
    }
}

// ---------------------------------------------------------------------------
extern "C" void kernel_launch(void* const* d_in, const int* in_sizes, int n_in,
                              void* d_out, int out_size) {
    const float* x  = (const float*)d_in[0];   // [4,16,1024]
    const float* cb = (const float*)d_in[1];   // [65536,16]
    float* out = (float*)d_out;

    prepA_kernel<<<PBLK, 256>>>(x, cb);
    prepB_kernel<<<NCODES / 256, 256>>>(cb);

    dim3 grid(4, NGR);
    scan_kernel<<<grid, 256>>>(x, cb);

    gather_kernel<<<GGRID, 256>>>(x, cb, out, out_size);
}

// round 14
// speedup vs baseline: 1.0293x; 1.0293x over previous
#include <cuda_runtime.h>
#include <math.h>
#include <stdint.h>
#include <limits.h>

// ---------------------------------------------------------------------------
// Quantizer: x [4,16,1024] f32, codebook [65536,16] f32.
// out[0:65536] = nearest codebook entry per token, [B,D,T]; out[65536] = loss.
//
// 3 launches, no intermediate DRAM table, no spills:
//   prepA : per-block |.| maxima partials
//   prepB : reduce partials -> scales; quantize codebook; reset state
//   scan  : PERSISTENT fused kernel (512 CTAs, all resident):
//           A: int8 dp4a tile maxima -> SMEM + atomicMax per-token int max
//           barrier; B: warp-cooperative exact fp32 rescue of candidates,
//           atomicMax packed (score,~idx) key (deterministic);
//           barrier; C: write output + fused deterministic loss
// ---------------------------------------------------------------------------

#define TOKENS   4096
#define NCODES   65536
#define DIM      16
#define STC      64                  // codes per tile
#define TPC      8                   // tiles per scan CTA
#define NGR      128                 // scan groups (grid.y)
#define SCTA     (4 * NGR)           // 512 CTAs (4/SM x 148 = 592 capacity)
#define PBLK     256
#define NINF     __int_as_float(0xff800000)
#define FULL     0xffffffffu
#define LSCALE   4294967296.0        // 2^32 fixed-point loss scale

__device__ float    g_part[PBLK * 4];
__device__ unsigned g_scal[4];            // maxX, maxC, SAc (float bits)
__device__ int4     g_Bq[NCODES];         // packed int8 codes, 1 MB
__device__ int      g_bias[NCODES];       // bias in int score units
__device__ int      g_imax[TOKENS];       // per-token int score max
__device__ unsigned long long g_best[TOKENS]; // packed (scoreOrd, ~idx)
__device__ unsigned g_bar;                // global barrier counter
__device__ unsigned long long g_lsum;
__device__ unsigned g_cnt;

__device__ __forceinline__ void cpasync16(const void* dst_smem, const void* src) {
    unsigned s = (unsigned)__cvta_generic_to_shared(dst_smem);
    asm volatile("cp.async.cg.shared.global [%0], [%1], 16;" :: "r"(s), "l"(src));
}
#define CP_COMMIT() asm volatile("cp.async.commit_group;")
#define CP_WAIT0()  asm volatile("cp.async.wait_group 0;")

__device__ __forceinline__ int pack4(int a0, int a1, int a2, int a3) {
    return (a0 & 0xFF) | ((a1 & 0xFF) << 8) | ((a2 & 0xFF) << 16) | (a3 << 24);
}

// ---------------------------------------------------------------------------
// prepA: per-block maxima of |x|, max|c|, Sum|c| -> g_part.
// ---------------------------------------------------------------------------
__global__ __launch_bounds__(256) void prepA_kernel(const float* __restrict__ x,
                                                    const float* __restrict__ cb) {
    __shared__ float sm[3][256];
    int i = blockIdx.x * 256 + threadIdx.x;          // 0..65535
    float ax = fabsf(x[i]);
    const float4* c4 = (const float4*)(cb + (size_t)i * DIM);
    float mc = 0.0f, sa = 0.0f;
#pragma unroll
    for (int v = 0; v < 4; v++) {
        float4 q = c4[v];
        float a0 = fabsf(q.x), a1 = fabsf(q.y), a2 = fabsf(q.z), a3 = fabsf(q.w);
        mc = fmaxf(fmaxf(mc, fmaxf(a0, a1)), fmaxf(a2, a3));
        sa += a0; sa += a1; sa += a2; sa += a3;
    }
    sm[0][threadIdx.x] = ax; sm[1][threadIdx.x] = mc; sm[2][threadIdx.x] = sa;
    __syncthreads();
    for (int s = 128; s > 0; s >>= 1) {
        if (threadIdx.x < s) {
#pragma unroll
            for (int k = 0; k < 3; k++)
                sm[k][threadIdx.x] = fmaxf(sm[k][threadIdx.x], sm[k][threadIdx.x + s]);
        }
        __syncthreads();
    }
    if (threadIdx.x < 3) g_part[blockIdx.x * 4 + threadIdx.x] = sm[threadIdx.x][0];
}

// ---------------------------------------------------------------------------
// prepB: reduce partials, publish scales, quantize codebook, reset state.
// ---------------------------------------------------------------------------
__global__ __launch_bounds__(256) void prepB_kernel(const float* __restrict__ cb) {
    __shared__ float sm[3][256];
    const int tid = threadIdx.x;
    sm[0][tid] = g_part[tid * 4 + 0];
    sm[1][tid] = g_part[tid * 4 + 1];
    sm[2][tid] = g_part[tid * 4 + 2];
    __syncthreads();
    for (int s = 128; s > 0; s >>= 1) {
        if (tid < s) {
#pragma unroll
            for (int k = 0; k < 3; k++)
                sm[k][tid] = fmaxf(sm[k][tid], sm[k][tid + s]);
        }
        __syncthreads();
    }
    const float maxX = sm[0][0], maxC = sm[1][0], SAc = sm[2][0];
    int gidx = blockIdx.x * 256 + tid;
    if (gidx < TOKENS) {                      // per-replay state reset
        g_imax[gidx] = INT_MIN;
        g_best[gidx] = 0ull;
    }
    if (gidx == 0) {
        g_scal[0] = __float_as_uint(maxX);
        g_scal[1] = __float_as_uint(maxC);
        g_scal[2] = __float_as_uint(SAc);
        g_bar  = 0u;
        g_lsum = 0ull;
        g_cnt  = 0u;
    }

    const float sx = maxX * (1.0f / 127.0f);
    const float sc = maxC * (1.0f / 127.0f);
    const float qc = 127.0f / maxC;
    const float4* c4 = (const float4*)(cb + (size_t)gidx * DIM);
    int q[DIM];
    float h = 0.0f;
#pragma unroll
    for (int v = 0; v < 4; v++) {
        float4 p = c4[v];
        h = fmaf(p.x, p.x, h); q[v * 4 + 0] = __float2int_rn(p.x * qc);
        h = fmaf(p.y, p.y, h); q[v * 4 + 1] = __float2int_rn(p.y * qc);
        h = fmaf(p.z, p.z, h); q[v * 4 + 2] = __float2int_rn(p.z * qc);
        h = fmaf(p.w, p.w, h); q[v * 4 + 3] = __float2int_rn(p.w * qc);
    }
    int4 w;
    w.x = pack4(q[0], q[1], q[2], q[3]);
    w.y = pack4(q[4], q[5], q[6], q[7]);
    w.z = pack4(q[8], q[9], q[10], q[11]);
    w.w = pack4(q[12], q[13], q[14], q[15]);
    g_Bq[gidx] = w;
    g_bias[gidx] = __float2int_rn(-0.5f * h / (sx * sc));
}

// ---------------------------------------------------------------------------
// scan: persistent fused kernel. grid (4, 128) = 512 CTAs, 256 thr,
// 4 CTAs/SM. Tile maxima live in SMEM (no register spills).
// ---------------------------------------------------------------------------
__global__ __launch_bounds__(256, 4) void scan_kernel(const float* __restrict__ x,
                                                      const float* __restrict__ cb,
                                                      float* __restrict__ out,
                                                      int out_size) {
    __shared__ int4 sQ[TPC * STC];          // 8 KB (512 code rows)
    __shared__ int  sB[TPC * STC];          // 2 KB
    __shared__ int  m_s[4 * TPC][256];      // 32 KB tile maxima

    const int tid  = threadIdx.x;
    const int lane = tid & 31;
    const int wbase = tid & ~31;
    const int batch = blockIdx.x;              // 0..3
    const int grp = blockIdx.y;                // 0..127
    const int c0 = grp * (TPC * STC);

    cpasync16(&sQ[tid], &g_Bq[c0 + tid]);
    cpasync16(&sQ[tid + 256], &g_Bq[c0 + tid + 256]);
    if (tid < 128) cpasync16(&sB[tid * 4], &g_bias[c0 + tid * 4]);
    CP_COMMIT();

    const float maxX = __uint_as_float(g_scal[0]);
    const float maxC = __uint_as_float(g_scal[1]);
    const float SAc  = __uint_as_float(g_scal[2]);
    const float sx = maxX * (1.0f / 127.0f);
    const float sc = maxC * (1.0f / 127.0f);
    const float s  = sx * sc;
    const float qx = 127.0f / maxX;

    // quantize 4 tokens; track Sum|x| per token for the error bound
    const float* xp = x + (size_t)batch * (DIM * 1024);
    int   xq[4][4];
    float sax[4];
#pragma unroll
    for (int tk = 0; tk < 4; tk++) {
        int t = tk * 256 + tid;
        float sa = 0.0f;
#pragma unroll
        for (int w = 0; w < 4; w++) {
            float f0 = xp[(w * 4 + 0) * 1024 + t];
            float f1 = xp[(w * 4 + 1) * 1024 + t];
            float f2 = xp[(w * 4 + 2) * 1024 + t];
            float f3 = xp[(w * 4 + 3) * 1024 + t];
            sa += fabsf(f0) + fabsf(f1) + fabsf(f2) + fabsf(f3);
            xq[tk][w] = pack4(__float2int_rn(f0 * qx), __float2int_rn(f1 * qx),
                              __float2int_rn(f2 * qx), __float2int_rn(f3 * qx));
        }
        sax[tk] = sa;
    }

    CP_WAIT0();
    __syncthreads();

    // ---- phase A: dp4a tile maxima -> SMEM; per-token max -> atomicMax ----
    int tmax[4];
#pragma unroll
    for (int tk = 0; tk < 4; tk++) tmax[tk] = INT_MIN;
    const int4* b4 = (const int4*)sB;
#pragma unroll
    for (int st = 0; st < TPC; st++) {
        int m[4];
#pragma unroll
        for (int tk = 0; tk < 4; tk++) m[tk] = INT_MIN;
#pragma unroll 4
        for (int g = 0; g < STC / 4; g++) {
            int4 bb = b4[st * (STC / 4) + g];
            int bias[4] = {bb.x, bb.y, bb.z, bb.w};
#pragma unroll
            for (int u = 0; u < 4; u++) {
                int4 q = sQ[st * STC + g * 4 + u];
#pragma unroll
                for (int tk = 0; tk < 4; tk++) {
                    int a = __dp4a(q.x, xq[tk][0], bias[u]);
                    a = __dp4a(q.y, xq[tk][1], a);
                    a = __dp4a(q.z, xq[tk][2], a);
                    a = __dp4a(q.w, xq[tk][3], a);
                    m[tk] = max(m[tk], a);
                }
            }
        }
#pragma unroll
        for (int tk = 0; tk < 4; tk++) {
            m_s[tk * TPC + st][tid] = m[tk];
            tmax[tk] = max(tmax[tk], m[tk]);
        }
    }

#pragma unroll
    for (int tk = 0; tk < 4; tk++)
        atomicMax(&g_imax[batch * 1024 + tk * 256 + tid], tmax[tk]);

    // ---- barrier 1 ----
    __syncthreads();
    if (tid == 0) {
        __threadfence();
        atomicAdd(&g_bar, 1u);
        while (*(volatile unsigned*)&g_bar < SCTA) { }
    }
    __syncthreads();
    __threadfence();

    // ---- phase B: warp-cooperative exact rescue of candidate tiles ----
    int thr[4];
#pragma unroll
    for (int tk = 0; tk < 4; tk++) {
        int imax = *(volatile int*)&g_imax[batch * 1024 + tk * 256 + tid];
        float E = 0.5f * sc * sax[tk] + 0.5f * sx * SAc
                + 16.0f * sx * sc + sx * sc + 1e-2f;
        thr[tk] = imax - (int)ceilf(2.0f * E / s);
    }

#pragma unroll
    for (int tk = 0; tk < 4; tk++) {
#pragma unroll
        for (int st = 0; st < TPC; st++) {
            unsigned bal = __ballot_sync(FULL, m_s[tk * TPC + st][tid] >= thr[tk]);
            while (bal) {
                int w = __ffs(bal) - 1;
                bal &= bal - 1;
                int tokw = batch * 1024 + tk * 256 + wbase + w;
                int tw = tokw & 1023;
                float xr[DIM];
#pragma unroll
                for (int d = 0; d < DIM; d++)       // broadcast loads, L2-hot
                    xr[d] = x[(size_t)batch * (DIM * 1024) + d * 1024 + tw];
                int cbase = (grp * TPC + st) * STC;
                float best = NINF;
                int   bi   = 0;
#pragma unroll
                for (int half = 0; half < 2; half++) {
                    int c = cbase + half * 32 + lane;
                    const float4* cr = (const float4*)(cb + (size_t)c * DIM);
                    float acc = 0.0f, h = 0.0f;
#pragma unroll
                    for (int v4 = 0; v4 < 4; v4++) {
                        float4 q = cr[v4];
                        acc = fmaf(q.x, xr[v4 * 4 + 0], acc); h = fmaf(q.x, q.x, h);
                        acc = fmaf(q.y, xr[v4 * 4 + 1], acc); h = fmaf(q.y, q.y, h);
                        acc = fmaf(q.z, xr[v4 * 4 + 2], acc); h = fmaf(q.z, q.z, h);
                        acc = fmaf(q.w, xr[v4 * 4 + 3], acc); h = fmaf(q.w, q.w, h);
                    }
                    float sscore = acc - 0.5f * h;
                    if (sscore > best || (sscore == best && c < bi)) {
                        best = sscore; bi = c;
                    }
                }
#pragma unroll
                for (int off = 16; off > 0; off >>= 1) {
                    float vb = __shfl_xor_sync(FULL, best, off);
                    int   ib = __shfl_xor_sync(FULL, bi,   off);
                    if (vb > best || (vb == best && ib < bi)) { best = vb; bi = ib; }
                }
                if (lane == 0) {
                    unsigned so = __float_as_uint(best);
                    so = (so & 0x80000000u) ? ~so : (so | 0x80000000u);
                    unsigned long long key =
                        ((unsigned long long)so << 32) | (unsigned)(~bi);
                    atomicMax(&g_best[tokw], key);   // max score, ties -> min idx
                }
            }
        }
    }

    // ---- barrier 2 ----
    __syncthreads();
    if (tid == 0) {
        __threadfence();
        atomicAdd(&g_bar, 1u);
        while (*(volatile unsigned*)&g_bar < 2 * SCTA) { }
    }
    __syncthreads();
    __threadfence();

    // ---- phase C: this CTA writes its 8 tokens + partial loss ----
    float ep = 0.0f;
    if (tid < 128) {
        int j = tid >> 4, d = tid & 15;
        int token = batch * 1024 + grp * 8 + j;
        int t = token & 1023;
        unsigned long long key = *(volatile unsigned long long*)&g_best[token];
        int code = (int)(~(unsigned)key);
        float qd = cb[(size_t)code * DIM + d];
        float xd = x[(size_t)batch * (DIM * 1024) + d * 1024 + t];
        out[(size_t)batch * (DIM * 1024) + d * 1024 + t] = qd;
        float df = qd - xd;
        ep = df * df;
    }
    float* shf = (float*)m_s;               // reuse smem for reduction
    shf[tid] = ep;
    __syncthreads();
    for (int stp = 128; stp > 0; stp >>= 1) {
        if (tid < stp) shf[tid] += shf[tid + stp];
        __syncthreads();
    }
    if (tid == 0) {
        unsigned long long r =
            (unsigned long long)__double2ll_rn((double)shf[0] * LSCALE);
        atomicAdd(&g_lsum, r);
        __threadfence();
        unsigned ticket = atomicAdd(&g_cnt, 1u);
        if (ticket == SCTA - 1 && out_size > NCODES) {
            double sum = (double)*(volatile unsigned long long*)&g_lsum;
            out[NCODES] = (float)(sum / LSCALE / (double)(TOKENS * DIM));
        }
    }
}

// ---------------------------------------------------------------------------
extern "C" void kernel_launch(void* const* d_in, const int* in_sizes, int n_in,
                              void* d_out, int out_size) {
    const float* x  = (const float*)d_in[0];   // [4,16,1024]
    const float* cb = (const float*)d_in[1];   // [65536,16]
    float* out = (float*)d_out;

    prepA_kernel<<<PBLK, 256>>>(x, cb);
    prepB_kernel<<<NCODES / 256, 256>>>(cb);

    dim3 grid(4, NGR);
    scan_kernel<<<grid, 256>>>(x, cb, out, out_size);
}